// round 14
// baseline (speedup 1.0000x reference)
#include <cuda_runtime.h>
#include <cuda_bf16.h>
#include <math.h>
#include <stdint.h>

namespace {

constexpr int B_  = 4;
constexpr int L_  = 2048;
constexpr int H_  = 16;
constexpr int E_  = 64;
constexpr int D_  = 64;
constexpr int TM  = 128;
constexpr int TN  = 128;
constexpr int NTQ = L_ / TM;            // 16
constexpr int RS  = H_ * E_;            // 1024
constexpr float QSCALE = 0.125f * 1.4426950408889634f;   // 1/sqrt(64) * log2(e)
constexpr size_t V_ELEMS = (size_t)B_ * L_ * H_ * D_;

// smem byte offsets
constexpr int QH_OFF = 0;        // [128][64] bf16 planes, 128B rows, XOR swizzle
constexpr int QL_OFF = 16384;
constexpr int KH_OFF = 32768;
constexpr int KL_OFF = 49152;
constexpr int VH_OFF = 65536;
constexpr int VL_OFF = 81920;
constexpr int FK_OFF = 98304;    // fp32 staging K tile [128][64]
constexpr int FV_OFF = 131072;   // fp32 staging V tile
constexpr int SMEM_BYTES = 163840;   // 160 KB

__device__ __forceinline__ void ldsm4(uint32_t r[4], uint32_t a) {
    asm volatile("ldmatrix.sync.aligned.m8n8.x4.shared.b16 {%0,%1,%2,%3}, [%4];"
        : "=r"(r[0]), "=r"(r[1]), "=r"(r[2]), "=r"(r[3]) : "r"(a));
}
__device__ __forceinline__ void ldsm4t(uint32_t r[4], uint32_t a) {
    asm volatile("ldmatrix.sync.aligned.m8n8.x4.trans.shared.b16 {%0,%1,%2,%3}, [%4];"
        : "=r"(r[0]), "=r"(r[1]), "=r"(r[2]), "=r"(r[3]) : "r"(a));
}
__device__ __forceinline__ void mma_bf16(float c[4], const uint32_t a[4],
                                         uint32_t b0, uint32_t b1) {
    asm volatile(
        "mma.sync.aligned.m16n8k16.row.col.f32.bf16.bf16.f32 "
        "{%0,%1,%2,%3}, {%4,%5,%6,%7}, {%8,%9}, {%0,%1,%2,%3};"
        : "+f"(c[0]), "+f"(c[1]), "+f"(c[2]), "+f"(c[3])
        : "r"(a[0]), "r"(a[1]), "r"(a[2]), "r"(a[3]), "r"(b0), "r"(b1));
}
__device__ __forceinline__ float ex2(float x) {
    float y;
    asm("ex2.approx.ftz.f32 %0, %1;" : "=f"(y) : "f"(x));
    return y;
}
__device__ __forceinline__ void cp16(uint32_t dst, const void* src) {
    asm volatile("cp.async.cg.shared.global [%0], [%1], 16;" :: "r"(dst), "l"(src));
}
__device__ __forceinline__ void cp_commit() {
    asm volatile("cp.async.commit_group;");
}
template <int N>
__device__ __forceinline__ void cp_wait() {
    asm volatile("cp.async.wait_group %0;" :: "n"(N));
}

__device__ __forceinline__ uint32_t pack2(float x, float y) {
    uint16_t hx = __bfloat16_as_ushort(__float2bfloat16_rn(x));
    uint16_t hy = __bfloat16_as_ushort(__float2bfloat16_rn(y));
    return (uint32_t)hx | ((uint32_t)hy << 16);
}
__device__ __forceinline__ void split2(float x, float y, uint32_t& hi, uint32_t& lo) {
    __nv_bfloat16 xh = __float2bfloat16_rn(x);
    __nv_bfloat16 yh = __float2bfloat16_rn(y);
    hi = (uint32_t)__bfloat16_as_ushort(xh) | ((uint32_t)__bfloat16_as_ushort(yh) << 16);
    lo = pack2(x - __bfloat162float(xh), y - __bfloat162float(yh));
}

// stage 128x64 fp32 tile from GLOBAL into hi/lo bf16 planes (for Q only)
__device__ __forceinline__ void stage_hl(const float* __restrict__ g,
                                         char* sm, int HOFF, int LOFF,
                                         int tid, float scale) {
    #pragma unroll
    for (int it = 0; it < 8; ++it) {
        int idx = it * 256 + tid;
        int n  = idx >> 4;
        int e4 = (idx & 15) << 2;
        float4 v = *(const float4*)(g + (size_t)n * RS + e4);
        v.x *= scale; v.y *= scale; v.z *= scale; v.w *= scale;
        uint32_t h0, l0, h1, l1;
        split2(v.x, v.y, h0, l0);
        split2(v.z, v.w, h1, l1);
        int ch  = (e4 >> 3) ^ (n & 7);
        int off = n * 128 + ch * 16 + (e4 & 4) * 2;
        *(uint2*)(sm + HOFF + off) = make_uint2(h0, h1);
        *(uint2*)(sm + LOFF + off) = make_uint2(l0, l1);
    }
}

// async prefetch: global fp32 tile -> smem staging buffer
__device__ __forceinline__ void prefetch_tile(const float* __restrict__ g,
                                              uint32_t dstb, int tid) {
    #pragma unroll
    for (int it = 0; it < 8; ++it) {
        int idx = it * 256 + tid;
        int n  = idx >> 4;
        int e4 = (idx & 15) << 2;
        cp16(dstb + (uint32_t)(n * 256 + e4 * 4), g + (size_t)n * RS + e4);
    }
}

// convert fp32 staging -> hi + lo planes
__device__ __forceinline__ void convert_hl(const char* src, char* sm,
                                           int HOFF, int LOFF, int tid) {
    const float* f = (const float*)src;
    #pragma unroll
    for (int it = 0; it < 8; ++it) {
        int idx = it * 256 + tid;
        int n  = idx >> 4;
        int e4 = (idx & 15) << 2;
        float4 v = *(const float4*)(f + n * 64 + e4);
        uint32_t h0, l0, h1, l1;
        split2(v.x, v.y, h0, l0);
        split2(v.z, v.w, h1, l1);
        int ch  = (e4 >> 3) ^ (n & 7);
        int off = n * 128 + ch * 16 + (e4 & 4) * 2;
        *(uint2*)(sm + HOFF + off) = make_uint2(h0, h1);
        *(uint2*)(sm + LOFF + off) = make_uint2(l0, l1);
    }
}

// 3-term split S — MUST be the unique score function for both passes
// (pass-1 (m,l) and pass-2 normalization need bitwise-identical scores)
__device__ __forceinline__ void compute_S3(float acc[16][4],
                                           const uint32_t qh[4][4], const uint32_t ql[4][4],
                                           uint32_t khb, uint32_t klb, int lane) {
    #pragma unroll
    for (int nt = 0; nt < 16; ++nt) {
        const int row = nt * 8 + (lane & 7);
        const uint32_t roff = row * 128;
        uint32_t kh0[4], kh1[4], kl0[4], kl1[4];
        ldsm4(kh0, khb + roff + ((uint32_t)(((lane >> 3)    ) ^ (row & 7)) << 4));
        ldsm4(kh1, khb + roff + ((uint32_t)((4 + (lane >> 3)) ^ (row & 7)) << 4));
        ldsm4(kl0, klb + roff + ((uint32_t)(((lane >> 3)    ) ^ (row & 7)) << 4));
        ldsm4(kl1, klb + roff + ((uint32_t)((4 + (lane >> 3)) ^ (row & 7)) << 4));
        float* c = acc[nt];
        mma_bf16(c, qh[0], kh0[0], kh0[1]);
        mma_bf16(c, qh[1], kh0[2], kh0[3]);
        mma_bf16(c, qh[2], kh1[0], kh1[1]);
        mma_bf16(c, qh[3], kh1[2], kh1[3]);
        mma_bf16(c, ql[0], kh0[0], kh0[1]);
        mma_bf16(c, ql[1], kh0[2], kh0[3]);
        mma_bf16(c, ql[2], kh1[0], kh1[1]);
        mma_bf16(c, ql[3], kh1[2], kh1[3]);
        mma_bf16(c, qh[0], kl0[0], kl0[1]);
        mma_bf16(c, qh[1], kl0[2], kl0[3]);
        mma_bf16(c, qh[2], kl1[0], kl1[1]);
        mma_bf16(c, qh[3], kl1[2], kl1[3]);
    }
}

__device__ __forceinline__ void mask_diag(float acc[16][4], int jTN,
                                          int grow0, int grow1, int cq) {
    #pragma unroll
    for (int nt = 0; nt < 16; ++nt) {
        int c0g = jTN + nt * 8 + cq;
        if (c0g     > grow0) acc[nt][0] = -1e30f;
        if (c0g + 1 > grow0) acc[nt][1] = -1e30f;
        if (c0g     > grow1) acc[nt][2] = -1e30f;
        if (c0g + 1 > grow1) acc[nt][3] = -1e30f;
    }
}

__global__ void __launch_bounds__(256, 1)
attn_mma(const float* __restrict__ Q, const float* __restrict__ K,
         const float* __restrict__ Vv, float* __restrict__ outV,
         float* __restrict__ outA)
{
    extern __shared__ char sm[];
    const int qt  = (NTQ - 1) - blockIdx.x;     // heavy tiles first
    const int bh  = blockIdx.y;
    const int b   = bh >> 4;
    const int h   = bh & 15;
    const int tid = threadIdx.x;
    const int wid = tid >> 5;
    const int lane = tid & 31;
    const int m0  = wid * 16;
    const int rq  = lane >> 2;
    const int cq  = (lane & 3) * 2;

    const uint32_t smb = (uint32_t)__cvta_generic_to_shared(sm);
    const float* Kbase = K  + ((size_t)(b * L_) * H_ + h) * E_;
    const float* Vbase = Vv + ((size_t)(b * L_) * H_ + h) * D_;

    // stage Q (pre-scaled into log2 domain), kick K tile-0 prefetch
    stage_hl(Q + ((size_t)(b * L_ + qt * TM) * H_ + h) * E_, sm, QH_OFF, QL_OFF, tid, QSCALE);
    prefetch_tile(Kbase, smb + FK_OFF, tid);
    cp_commit();
    __syncthreads();

    // persistent Q fragments (hi + lo)
    uint32_t qh[4][4], ql[4][4];
    #pragma unroll
    for (int ks = 0; ks < 4; ++ks) {
        int row = m0 + (lane & 7) + ((lane >> 3) & 1) * 8;
        int ch  = 2 * ks + (lane >> 4);
        uint32_t off = row * 128 + ((uint32_t)(ch ^ (row & 7)) << 4);
        ldsm4(qh[ks], smb + QH_OFF + off);
        ldsm4(ql[ks], smb + QL_OFF + off);
    }

    const int grow0 = qt * TM + m0 + rq;
    const int grow1 = grow0 + 8;

    float m_run[2] = {-1e30f, -1e30f};
    float l_run[2] = {0.0f, 0.0f};

    // =================== pass 1: stats only (3-term, identical to pass 2) ===================
    for (int j = 0; j <= qt; ++j) {
        cp_wait<0>();
        __syncthreads();                      // staging arrived; KH/KL free
        convert_hl(sm + FK_OFF, sm, KH_OFF, KL_OFF, tid);
        __syncthreads();                      // KH/KL ready; staging free
        if (j < qt) {
            prefetch_tile(Kbase + (size_t)(j + 1) * TN * RS, smb + FK_OFF, tid);
            cp_commit();
        }

        float acc[16][4];
        #pragma unroll
        for (int nt = 0; nt < 16; ++nt)
            #pragma unroll
            for (int e = 0; e < 4; ++e) acc[nt][e] = 0.0f;

        compute_S3(acc, qh, ql, smb + KH_OFF, smb + KL_OFF, lane);
        if (j == qt) mask_diag(acc, j * TN, grow0, grow1, cq);

        float mx0 = -1e30f, mx1 = -1e30f;
        #pragma unroll
        for (int nt = 0; nt < 16; ++nt) {
            mx0 = fmaxf(mx0, fmaxf(acc[nt][0], acc[nt][1]));
            mx1 = fmaxf(mx1, fmaxf(acc[nt][2], acc[nt][3]));
        }
        mx0 = fmaxf(mx0, __shfl_xor_sync(0xffffffffu, mx0, 1));
        mx0 = fmaxf(mx0, __shfl_xor_sync(0xffffffffu, mx0, 2));
        mx1 = fmaxf(mx1, __shfl_xor_sync(0xffffffffu, mx1, 1));
        mx1 = fmaxf(mx1, __shfl_xor_sync(0xffffffffu, mx1, 2));
        float mn0 = fmaxf(m_run[0], mx0);
        float mn1 = fmaxf(m_run[1], mx1);
        float s0 = 0.0f, s1 = 0.0f;
        #pragma unroll
        for (int nt = 0; nt < 16; ++nt) {
            s0 += ex2(acc[nt][0] - mn0) + ex2(acc[nt][1] - mn0);
            s1 += ex2(acc[nt][2] - mn1) + ex2(acc[nt][3] - mn1);
        }
        s0 += __shfl_xor_sync(0xffffffffu, s0, 1);
        s0 += __shfl_xor_sync(0xffffffffu, s0, 2);
        s1 += __shfl_xor_sync(0xffffffffu, s1, 1);
        s1 += __shfl_xor_sync(0xffffffffu, s1, 2);
        l_run[0] = l_run[0] * ex2(m_run[0] - mn0) + s0;  m_run[0] = mn0;
        l_run[1] = l_run[1] * ex2(m_run[1] - mn1) + s1;  m_run[1] = mn1;
    }
    const float inv_l0 = 1.0f / l_run[0];
    const float inv_l1 = 1.0f / l_run[1];

    // prefetch pass-2 tile 0 (K and V) — overlaps with zero-fill below
    prefetch_tile(Kbase, smb + FK_OFF, tid);
    prefetch_tile(Vbase, smb + FV_OFF, tid);
    cp_commit();

    // =================== zero strictly-upper tiles of A ===================
    float* aBase = outA + ((size_t)bh * L_ + (size_t)qt * TM) * L_;
    for (int j = qt + 1; j < NTQ; ++j) {
        #pragma unroll
        for (int it = 0; it < 16; ++it) {
            int idx = it * 256 + tid;
            int r   = idx >> 5;
            int c4  = (idx & 31) << 2;
            *(float4*)(aBase + (size_t)r * L_ + j * TN + c4) = make_float4(0.f, 0.f, 0.f, 0.f);
        }
    }

    // =================== pass 2: recompute (3-term), write A, PV ===================
    float o[8][4];
    #pragma unroll
    for (int dt = 0; dt < 8; ++dt)
        #pragma unroll
        for (int e = 0; e < 4; ++e) o[dt][e] = 0.0f;

    for (int j = 0; j <= qt; ++j) {
        cp_wait<0>();
        __syncthreads();
        convert_hl(sm + FK_OFF, sm, KH_OFF, KL_OFF, tid);
        convert_hl(sm + FV_OFF, sm, VH_OFF, VL_OFF, tid);
        __syncthreads();
        if (j < qt) {
            prefetch_tile(Kbase + (size_t)(j + 1) * TN * RS, smb + FK_OFF, tid);
            prefetch_tile(Vbase + (size_t)(j + 1) * TN * RS, smb + FV_OFF, tid);
            cp_commit();
        }

        float acc[16][4];
        #pragma unroll
        for (int nt = 0; nt < 16; ++nt)
            #pragma unroll
            for (int e = 0; e < 4; ++e) acc[nt][e] = 0.0f;

        compute_S3(acc, qh, ql, smb + KH_OFF, smb + KL_OFF, lane);
        if (j == qt) mask_diag(acc, j * TN, grow0, grow1, cq);

        // fused per-quarter: normalize -> write A -> split -> PV MMAs
        // (P fragments live only 16 regs at a time)
        const int r_lo = m0 + rq;
        #pragma unroll
        for (int q4 = 0; q4 < 4; ++q4) {
            uint32_t ph[2][4], pl[2][4];
            #pragma unroll
            for (int t = 0; t < 4; ++t) {
                const int nt = 4 * q4 + t;
                float p00 = ex2(acc[nt][0] - m_run[0]) * inv_l0;
                float p01 = ex2(acc[nt][1] - m_run[0]) * inv_l0;
                float p10 = ex2(acc[nt][2] - m_run[1]) * inv_l1;
                float p11 = ex2(acc[nt][3] - m_run[1]) * inv_l1;
                int c = nt * 8 + cq;
                float* a0p = aBase + (size_t)r_lo * L_ + j * TN + c;
                *(float2*)a0p            = make_float2(p00, p01);
                *(float2*)(a0p + 8 * L_) = make_float2(p10, p11);
                const int kc = t >> 1;
                const int hf = (t & 1) * 2;
                split2(p00, p01, ph[kc][hf],     pl[kc][hf]);
                split2(p10, p11, ph[kc][hf + 1], pl[kc][hf + 1]);
            }
            const int row = q4 * 32 + lane;
            #pragma unroll
            for (int dt = 0; dt < 8; ++dt) {
                uint32_t off = row * 128 + ((uint32_t)(dt ^ (row & 7)) << 4);
                uint32_t vh[4], vl[4];
                ldsm4t(vh, smb + VH_OFF + off);
                ldsm4t(vl, smb + VL_OFF + off);
                mma_bf16(o[dt], ph[0], vh[0], vh[1]);
                mma_bf16(o[dt], ph[1], vh[2], vh[3]);
                mma_bf16(o[dt], ph[0], vl[0], vl[1]);
                mma_bf16(o[dt], ph[1], vl[2], vl[3]);
                mma_bf16(o[dt], pl[0], vh[0], vh[1]);
                mma_bf16(o[dt], pl[1], vh[2], vh[3]);
            }
        }
    }

    // ---- write V output [B, L, H, D] ----
    float* vout = outV + ((size_t)(b * L_ + qt * TM) * H_ + h) * D_;
    #pragma unroll
    for (int dt = 0; dt < 8; ++dt) {
        int d = dt * 8 + cq;
        float* p0 = vout + (size_t)(m0 + rq) * RS + d;
        *(float2*)p0            = make_float2(o[dt][0], o[dt][1]);
        *(float2*)(p0 + 8 * RS) = make_float2(o[dt][2], o[dt][3]);
    }
}

} // namespace

extern "C" void kernel_launch(void* const* d_in, const int* in_sizes, int n_in,
                              void* d_out, int out_size)
{
    const float* Q = (const float*)d_in[0];
    const float* K = (const float*)d_in[1];
    const float* V = (const float*)d_in[2];
    float* outV = (float*)d_out;
    float* outA = outV + V_ELEMS;

    cudaFuncSetAttribute(attn_mma, cudaFuncAttributeMaxDynamicSharedMemorySize, SMEM_BYTES);
    dim3 grid(NTQ, B_ * H_);
    attn_mma<<<grid, 256, SMEM_BYTES>>>(Q, K, V, outV, outA);
}

// round 15
// speedup vs baseline: 1.5472x; 1.5472x over previous
#include <cuda_runtime.h>
#include <cuda_bf16.h>
#include <math.h>
#include <stdint.h>

namespace {

constexpr int B_  = 4;
constexpr int L_  = 2048;
constexpr int H_  = 16;
constexpr int E_  = 64;
constexpr int D_  = 64;
constexpr int TM  = 128;
constexpr int TN  = 128;
constexpr int NTQ = L_ / TM;            // 16
constexpr int RS  = H_ * E_;            // 1024
constexpr float QSCALE = 0.125f * 1.4426950408889634f;   // 1/sqrt(64) * log2(e)
constexpr size_t V_ELEMS = (size_t)B_ * L_ * H_ * D_;

// smem byte offsets
constexpr int QH_OFF = 0;        // [128][64] bf16 planes, 128B rows, XOR swizzle
constexpr int QL_OFF = 16384;
constexpr int KH_OFF = 32768;
constexpr int KL_OFF = 49152;
constexpr int VH_OFF = 65536;
constexpr int VL_OFF = 81920;
constexpr int FK_OFF = 98304;    // fp32 staging K tile [128][64]
constexpr int FV_OFF = 131072;   // fp32 staging V tile
constexpr int SMEM_BYTES = 163840;   // 160 KB

__device__ __forceinline__ void ldsm4(uint32_t r[4], uint32_t a) {
    asm volatile("ldmatrix.sync.aligned.m8n8.x4.shared.b16 {%0,%1,%2,%3}, [%4];"
        : "=r"(r[0]), "=r"(r[1]), "=r"(r[2]), "=r"(r[3]) : "r"(a));
}
__device__ __forceinline__ void ldsm4t(uint32_t r[4], uint32_t a) {
    asm volatile("ldmatrix.sync.aligned.m8n8.x4.trans.shared.b16 {%0,%1,%2,%3}, [%4];"
        : "=r"(r[0]), "=r"(r[1]), "=r"(r[2]), "=r"(r[3]) : "r"(a));
}
__device__ __forceinline__ void mma_bf16(float c[4], const uint32_t a[4],
                                         uint32_t b0, uint32_t b1) {
    asm volatile(
        "mma.sync.aligned.m16n8k16.row.col.f32.bf16.bf16.f32 "
        "{%0,%1,%2,%3}, {%4,%5,%6,%7}, {%8,%9}, {%0,%1,%2,%3};"
        : "+f"(c[0]), "+f"(c[1]), "+f"(c[2]), "+f"(c[3])
        : "r"(a[0]), "r"(a[1]), "r"(a[2]), "r"(a[3]), "r"(b0), "r"(b1));
}
__device__ __forceinline__ float ex2(float x) {
    float y;
    asm("ex2.approx.ftz.f32 %0, %1;" : "=f"(y) : "f"(x));
    return y;
}
__device__ __forceinline__ void cp16(uint32_t dst, const void* src) {
    asm volatile("cp.async.cg.shared.global [%0], [%1], 16;" :: "r"(dst), "l"(src));
}
__device__ __forceinline__ void cp_commit() {
    asm volatile("cp.async.commit_group;");
}
template <int N>
__device__ __forceinline__ void cp_wait() {
    asm volatile("cp.async.wait_group %0;" :: "n"(N));
}

__device__ __forceinline__ uint32_t pack2(float x, float y) {
    uint16_t hx = __bfloat16_as_ushort(__float2bfloat16_rn(x));
    uint16_t hy = __bfloat16_as_ushort(__float2bfloat16_rn(y));
    return (uint32_t)hx | ((uint32_t)hy << 16);
}
__device__ __forceinline__ void split2(float x, float y, uint32_t& hi, uint32_t& lo) {
    __nv_bfloat16 xh = __float2bfloat16_rn(x);
    __nv_bfloat16 yh = __float2bfloat16_rn(y);
    hi = (uint32_t)__bfloat16_as_ushort(xh) | ((uint32_t)__bfloat16_as_ushort(yh) << 16);
    lo = pack2(x - __bfloat162float(xh), y - __bfloat162float(yh));
}

// stage 128x64 fp32 tile from GLOBAL into hi/lo bf16 planes (for Q only)
__device__ __forceinline__ void stage_hl(const float* __restrict__ g,
                                         char* sm, int HOFF, int LOFF,
                                         int tid, float scale) {
    #pragma unroll
    for (int it = 0; it < 8; ++it) {
        int idx = it * 256 + tid;
        int n  = idx >> 4;
        int e4 = (idx & 15) << 2;
        float4 v = *(const float4*)(g + (size_t)n * RS + e4);
        v.x *= scale; v.y *= scale; v.z *= scale; v.w *= scale;
        uint32_t h0, l0, h1, l1;
        split2(v.x, v.y, h0, l0);
        split2(v.z, v.w, h1, l1);
        int ch  = (e4 >> 3) ^ (n & 7);
        int off = n * 128 + ch * 16 + (e4 & 4) * 2;
        *(uint2*)(sm + HOFF + off) = make_uint2(h0, h1);
        *(uint2*)(sm + LOFF + off) = make_uint2(l0, l1);
    }
}

// async prefetch: global fp32 tile -> smem staging buffer
__device__ __forceinline__ void prefetch_tile(const float* __restrict__ g,
                                              uint32_t dstb, int tid) {
    #pragma unroll
    for (int it = 0; it < 8; ++it) {
        int idx = it * 256 + tid;
        int n  = idx >> 4;
        int e4 = (idx & 15) << 2;
        cp16(dstb + (uint32_t)(n * 256 + e4 * 4), g + (size_t)n * RS + e4);
    }
}

// convert fp32 staging -> hi + lo planes
__device__ __forceinline__ void convert_hl(const char* src, char* sm,
                                           int HOFF, int LOFF, int tid) {
    const float* f = (const float*)src;
    #pragma unroll
    for (int it = 0; it < 8; ++it) {
        int idx = it * 256 + tid;
        int n  = idx >> 4;
        int e4 = (idx & 15) << 2;
        float4 v = *(const float4*)(f + n * 64 + e4);
        uint32_t h0, l0, h1, l1;
        split2(v.x, v.y, h0, l0);
        split2(v.z, v.w, h1, l1);
        int ch  = (e4 >> 3) ^ (n & 7);
        int off = n * 128 + ch * 16 + (e4 & 4) * 2;
        *(uint2*)(sm + HOFF + off) = make_uint2(h0, h1);
        *(uint2*)(sm + LOFF + off) = make_uint2(l0, l1);
    }
}

// 3-term split S — MUST be the unique score function for both passes
// (pass-1 (m,l) and pass-2 normalization need bitwise-identical scores)
__device__ __forceinline__ void compute_S3(float acc[16][4],
                                           const uint32_t qh[4][4], const uint32_t ql[4][4],
                                           uint32_t khb, uint32_t klb, int lane) {
    #pragma unroll
    for (int nt = 0; nt < 16; ++nt) {
        const int row = nt * 8 + (lane & 7);
        const uint32_t roff = row * 128;
        uint32_t kh0[4], kh1[4], kl0[4], kl1[4];
        ldsm4(kh0, khb + roff + ((uint32_t)(((lane >> 3)    ) ^ (row & 7)) << 4));
        ldsm4(kh1, khb + roff + ((uint32_t)((4 + (lane >> 3)) ^ (row & 7)) << 4));
        ldsm4(kl0, klb + roff + ((uint32_t)(((lane >> 3)    ) ^ (row & 7)) << 4));
        ldsm4(kl1, klb + roff + ((uint32_t)((4 + (lane >> 3)) ^ (row & 7)) << 4));
        float* c = acc[nt];
        mma_bf16(c, qh[0], kh0[0], kh0[1]);
        mma_bf16(c, qh[1], kh0[2], kh0[3]);
        mma_bf16(c, qh[2], kh1[0], kh1[1]);
        mma_bf16(c, qh[3], kh1[2], kh1[3]);
        mma_bf16(c, ql[0], kh0[0], kh0[1]);
        mma_bf16(c, ql[1], kh0[2], kh0[3]);
        mma_bf16(c, ql[2], kh1[0], kh1[1]);
        mma_bf16(c, ql[3], kh1[2], kh1[3]);
        mma_bf16(c, qh[0], kl0[0], kl0[1]);
        mma_bf16(c, qh[1], kl0[2], kl0[3]);
        mma_bf16(c, qh[2], kl1[0], kl1[1]);
        mma_bf16(c, qh[3], kl1[2], kl1[3]);
    }
}

__device__ __forceinline__ void mask_diag(float acc[16][4], int jTN,
                                          int grow0, int grow1, int cq) {
    #pragma unroll
    for (int nt = 0; nt < 16; ++nt) {
        int c0g = jTN + nt * 8 + cq;
        if (c0g     > grow0) acc[nt][0] = -1e30f;
        if (c0g + 1 > grow0) acc[nt][1] = -1e30f;
        if (c0g     > grow1) acc[nt][2] = -1e30f;
        if (c0g + 1 > grow1) acc[nt][3] = -1e30f;
    }
}

__global__ void __launch_bounds__(256, 1)
attn_mma(const float* __restrict__ Q, const float* __restrict__ K,
         const float* __restrict__ Vv, float* __restrict__ outV,
         float* __restrict__ outA)
{
    extern __shared__ char sm[];
    const int qt  = (NTQ - 1) - blockIdx.x;     // heavy tiles first
    const int bh  = blockIdx.y;
    const int b   = bh >> 4;
    const int h   = bh & 15;
    const int tid = threadIdx.x;
    const int wid = tid >> 5;
    const int lane = tid & 31;
    const int m0  = wid * 16;
    const int rq  = lane >> 2;
    const int cq  = (lane & 3) * 2;

    const uint32_t smb = (uint32_t)__cvta_generic_to_shared(sm);
    const float* Kbase = K  + ((size_t)(b * L_) * H_ + h) * E_;
    const float* Vbase = Vv + ((size_t)(b * L_) * H_ + h) * D_;

    // stage Q (pre-scaled into log2 domain), kick K tile-0 prefetch
    stage_hl(Q + ((size_t)(b * L_ + qt * TM) * H_ + h) * E_, sm, QH_OFF, QL_OFF, tid, QSCALE);
    prefetch_tile(Kbase, smb + FK_OFF, tid);
    cp_commit();
    __syncthreads();

    // persistent Q fragments (hi + lo)
    uint32_t qh[4][4], ql[4][4];
    #pragma unroll
    for (int ks = 0; ks < 4; ++ks) {
        int row = m0 + (lane & 7) + ((lane >> 3) & 1) * 8;
        int ch  = 2 * ks + (lane >> 4);
        uint32_t off = row * 128 + ((uint32_t)(ch ^ (row & 7)) << 4);
        ldsm4(qh[ks], smb + QH_OFF + off);
        ldsm4(ql[ks], smb + QL_OFF + off);
    }

    const int grow0 = qt * TM + m0 + rq;
    const int grow1 = grow0 + 8;

    float m_run[2] = {-1e30f, -1e30f};
    float l_run[2] = {0.0f, 0.0f};

    // =================== pass 1: stats only (3-term, identical to pass 2) ===================
    for (int j = 0; j <= qt; ++j) {
        cp_wait<0>();
        __syncthreads();                      // staging arrived; KH/KL free
        convert_hl(sm + FK_OFF, sm, KH_OFF, KL_OFF, tid);
        __syncthreads();                      // KH/KL ready; staging free
        if (j < qt) {
            prefetch_tile(Kbase + (size_t)(j + 1) * TN * RS, smb + FK_OFF, tid);
            cp_commit();
        }

        float acc[16][4];
        #pragma unroll
        for (int nt = 0; nt < 16; ++nt)
            #pragma unroll
            for (int e = 0; e < 4; ++e) acc[nt][e] = 0.0f;

        compute_S3(acc, qh, ql, smb + KH_OFF, smb + KL_OFF, lane);
        if (j == qt) mask_diag(acc, j * TN, grow0, grow1, cq);

        float mx0 = -1e30f, mx1 = -1e30f;
        #pragma unroll
        for (int nt = 0; nt < 16; ++nt) {
            mx0 = fmaxf(mx0, fmaxf(acc[nt][0], acc[nt][1]));
            mx1 = fmaxf(mx1, fmaxf(acc[nt][2], acc[nt][3]));
        }
        mx0 = fmaxf(mx0, __shfl_xor_sync(0xffffffffu, mx0, 1));
        mx0 = fmaxf(mx0, __shfl_xor_sync(0xffffffffu, mx0, 2));
        mx1 = fmaxf(mx1, __shfl_xor_sync(0xffffffffu, mx1, 1));
        mx1 = fmaxf(mx1, __shfl_xor_sync(0xffffffffu, mx1, 2));
        float mn0 = fmaxf(m_run[0], mx0);
        float mn1 = fmaxf(m_run[1], mx1);
        float s0 = 0.0f, s1 = 0.0f;
        #pragma unroll
        for (int nt = 0; nt < 16; ++nt) {
            s0 += ex2(acc[nt][0] - mn0) + ex2(acc[nt][1] - mn0);
            s1 += ex2(acc[nt][2] - mn1) + ex2(acc[nt][3] - mn1);
        }
        s0 += __shfl_xor_sync(0xffffffffu, s0, 1);
        s0 += __shfl_xor_sync(0xffffffffu, s0, 2);
        s1 += __shfl_xor_sync(0xffffffffu, s1, 1);
        s1 += __shfl_xor_sync(0xffffffffu, s1, 2);
        l_run[0] = l_run[0] * ex2(m_run[0] - mn0) + s0;  m_run[0] = mn0;
        l_run[1] = l_run[1] * ex2(m_run[1] - mn1) + s1;  m_run[1] = mn1;
    }
    const float inv_l0 = 1.0f / l_run[0];
    const float inv_l1 = 1.0f / l_run[1];

    // prefetch pass-2 tile 0 (K and V) — overlaps with zero-fill below
    prefetch_tile(Kbase, smb + FK_OFF, tid);
    prefetch_tile(Vbase, smb + FV_OFF, tid);
    cp_commit();

    // =================== zero strictly-upper tiles of A ===================
    float* aBase = outA + ((size_t)bh * L_ + (size_t)qt * TM) * L_;
    for (int j = qt + 1; j < NTQ; ++j) {
        #pragma unroll
        for (int it = 0; it < 16; ++it) {
            int idx = it * 256 + tid;
            int r   = idx >> 5;
            int c4  = (idx & 31) << 2;
            *(float4*)(aBase + (size_t)r * L_ + j * TN + c4) = make_float4(0.f, 0.f, 0.f, 0.f);
        }
    }

    // =================== pass 2: recompute (3-term), write A, PV ===================
    float o[8][4];
    #pragma unroll
    for (int dt = 0; dt < 8; ++dt)
        #pragma unroll
        for (int e = 0; e < 4; ++e) o[dt][e] = 0.0f;

    for (int j = 0; j <= qt; ++j) {
        cp_wait<0>();
        __syncthreads();
        convert_hl(sm + FK_OFF, sm, KH_OFF, KL_OFF, tid);
        convert_hl(sm + FV_OFF, sm, VH_OFF, VL_OFF, tid);
        __syncthreads();
        if (j < qt) {
            prefetch_tile(Kbase + (size_t)(j + 1) * TN * RS, smb + FK_OFF, tid);
            prefetch_tile(Vbase + (size_t)(j + 1) * TN * RS, smb + FV_OFF, tid);
            cp_commit();
        }

        float acc[16][4];
        #pragma unroll
        for (int nt = 0; nt < 16; ++nt)
            #pragma unroll
            for (int e = 0; e < 4; ++e) acc[nt][e] = 0.0f;

        compute_S3(acc, qh, ql, smb + KH_OFF, smb + KL_OFF, lane);
        if (j == qt) mask_diag(acc, j * TN, grow0, grow1, cq);

        // fused per-quarter: normalize -> write A -> split -> PV MMAs
        // (P fragments live only 16 regs at a time)
        const int r_lo = m0 + rq;
        #pragma unroll
        for (int q4 = 0; q4 < 4; ++q4) {
            uint32_t ph[2][4], pl[2][4];
            #pragma unroll
            for (int t = 0; t < 4; ++t) {
                const int nt = 4 * q4 + t;
                float p00 = ex2(acc[nt][0] - m_run[0]) * inv_l0;
                float p01 = ex2(acc[nt][1] - m_run[0]) * inv_l0;
                float p10 = ex2(acc[nt][2] - m_run[1]) * inv_l1;
                float p11 = ex2(acc[nt][3] - m_run[1]) * inv_l1;
                int c = nt * 8 + cq;
                float* a0p = aBase + (size_t)r_lo * L_ + j * TN + c;
                *(float2*)a0p            = make_float2(p00, p01);
                *(float2*)(a0p + 8 * L_) = make_float2(p10, p11);
                const int kc = t >> 1;
                const int hf = (t & 1) * 2;
                split2(p00, p01, ph[kc][hf],     pl[kc][hf]);
                split2(p10, p11, ph[kc][hf + 1], pl[kc][hf + 1]);
            }
            const int row = q4 * 32 + lane;
            #pragma unroll
            for (int dt = 0; dt < 8; ++dt) {
                uint32_t off = row * 128 + ((uint32_t)(dt ^ (row & 7)) << 4);
                uint32_t vh[4], vl[4];
                ldsm4t(vh, smb + VH_OFF + off);
                ldsm4t(vl, smb + VL_OFF + off);
                mma_bf16(o[dt], ph[0], vh[0], vh[1]);
                mma_bf16(o[dt], ph[1], vh[2], vh[3]);
                mma_bf16(o[dt], ph[0], vl[0], vl[1]);
                mma_bf16(o[dt], ph[1], vl[2], vl[3]);
                mma_bf16(o[dt], pl[0], vh[0], vh[1]);
                mma_bf16(o[dt], pl[1], vh[2], vh[3]);
            }
        }
    }

    // ---- write V output [B, L, H, D] ----
    float* vout = outV + ((size_t)(b * L_ + qt * TM) * H_ + h) * D_;
    #pragma unroll
    for (int dt = 0; dt < 8; ++dt) {
        int d = dt * 8 + cq;
        float* p0 = vout + (size_t)(m0 + rq) * RS + d;
        *(float2*)p0            = make_float2(o[dt][0], o[dt][1]);
        *(float2*)(p0 + 8 * RS) = make_float2(o[dt][2], o[dt][3]);
    }
}

} // namespace

extern "C" void kernel_launch(void* const* d_in, const int* in_sizes, int n_in,
                              void* d_out, int out_size)
{
    const float* Q = (const float*)d_in[0];
    const float* K = (const float*)d_in[1];
    const float* V = (const float*)d_in[2];
    float* outV = (float*)d_out;
    float* outA = outV + V_ELEMS;

    cudaFuncSetAttribute(attn_mma, cudaFuncAttributeMaxDynamicSharedMemorySize, SMEM_BYTES);
    dim3 grid(NTQ, B_ * H_);
    attn_mma<<<grid, 256, SMEM_BYTES>>>(Q, K, V, outV, outA);
}